// round 11
// baseline (speedup 1.0000x reference)
#include <cuda_runtime.h>

#define D      256
#define NDAY   7
#define NT     288
#define NC     (NDAY * NT)        // 2016 distinct (day, tod) combos
#define ROWS   (64 * 2048)        // B * S = 131072
#define MTILE  16                 // combos per m-block
#define NMB    (NC / MTILE)       // 126 m-blocks
#define KSPLIT 8                  // k-eighths
#define KQ     (D / KSPLIT)       // 32 k-values per build task
#define MPT    (MTILE / 2)        // 8 combos per thread (2 column-halves)
#define CAP    256                // bucket capacity (mean 65, max ~105)

#define NTASK_SCAT  (ROWS / 256)              // 512 scatter tasks
#define NTASK_BUILD (NMB * KSPLIT)            // 1008 build tasks
#define NTASKS      (NTASK_SCAT + NTASK_BUILD)// 1520 builder tasks

#define NWRITERS  296            // 1/3 of chip: DRAM-bound side
#define NBUILDERS 592            // 2/3 of chip: FMA-bound side
#define GRID      (NWRITERS + NBUILDERS)      // 888 = 6 CTAs/SM x 148 SMs

// K-split partial sums of the combo table. 8 x 2 MB. b2 folded into part 0.
__device__ float    g_part[KSPLIT][NC * D];
// Per-combo row buckets (self-resetting).
__device__ int      g_cnt[NC];
__device__ int      g_rowlist[NC * CAP];
// Pipeline state (all self-resetting; zero at module load).
__device__ unsigned g_task;               // builder work queue head
__device__ unsigned g_scat_done;          // target NTASK_SCAT
__device__ unsigned g_done_mb[NMB];       // target KSPLIT
__device__ unsigned g_wpass_mb[NMB];      // MTILE write-combos per mb
__device__ unsigned g_wpass_total;        // NC write-combos overall

// -------------------------------------------------------------------------
// Persistent one-wave kernel. __launch_bounds__(256, 6) guarantees 6 CTAs/SM
// are co-resident, so GRID = 888 is exactly one wave: writer CTAs may spin
// without ever starving builder CTAs (all builders are resident from t=0).
//
//   blocks [0, 592):   builders — pull tasks (512 scatter, then 1008 build
//                      partials in mb-major order) from an atomic queue.
//   blocks [592, 888): writers — for combos c = w, w+296, ...: wait for
//                      scatter + this mb's 8 builds, reduce partials, and
//                      stream the 1 KB row to every bucket row (__stcs).
// DRAM writes overlap the remaining FMA builds (disjoint resources).
// -------------------------------------------------------------------------
__global__ void __launch_bounds__(256, 6) fused_pipeline(
    const float* __restrict__ W1, const float* __restrict__ b1,
    const float* __restrict__ W2, const float* __restrict__ b2,
    const void* __restrict__ TEp, float* __restrict__ out)
{
    const int bx  = blockIdx.x;
    const int tid = threadIdx.x;

    if (bx < NBUILDERS) {
        // ============================ builder ============================
        __shared__ __align__(16) float h_sh[MTILE][KQ];   // 2 KB
        __shared__ unsigned s_task;

        for (;;) {
            if (tid == 0) s_task = atomicAdd(&g_task, 1u);
            __syncthreads();
            const unsigned task = s_task;
            __syncthreads();
            if (task >= (unsigned)NTASKS) break;

            if (task < (unsigned)NTASK_SCAT) {
                // ---- scatter task: 256 rows ----
                // Per-warp TE dtype detect: values 0..287 -> int64 layout has
                // all-zero high 32-bit words; int32 layout has random values.
                const int lane = tid & 31;
                const unsigned long long* TE64 = (const unsigned long long*)TEp;
                unsigned long long hv = (TE64[lane] >> 32) | (TE64[lane + 32] >> 32);
                bool is64 = (__ballot_sync(0xffffffffu, hv != 0ULL) == 0u);

                const int row = (int)task * 256 + tid;
                int t0, t1;
                if (is64) {
                    longlong2 te = reinterpret_cast<const longlong2*>(TEp)[row];
                    t0 = (int)te.x; t1 = (int)te.y;
                } else {
                    int2 te = reinterpret_cast<const int2*>(TEp)[row];
                    t0 = te.x; t1 = te.y;
                }
                int day = t0 % NDAY; day += (day >> 31) & NDAY;
                int tod = t1 % NT;   tod += (tod >> 31) & NT;
                int c   = day * NT + tod;
                int slot = atomicAdd(&g_cnt[c], 1);
                if (slot < CAP) g_rowlist[c * CAP + slot] = row;

                __threadfence();
                __syncthreads();
                if (tid == 0) atomicAdd(&g_scat_done, 1u);
            } else {
                // ---- build task: partial GEMM for (mb, ks) ----
                const int b  = (int)task - NTASK_SCAT;
                const int mb = b >> 3;
                const int ks = b & 7;
                const int c0 = mb * MTILE;
                const int k0 = ks * KQ;

                // Phase 1: h slice. 16*32 = 512 values, 256 threads.
                #pragma unroll
                for (int it = 0; it < (MTILE * KQ) / 256; it++) {
                    int idx = it * 256 + tid;
                    int m   = idx >> 5;            // /KQ
                    int kk  = idx & (KQ - 1);
                    int c   = c0 + m;
                    int day = c / NT;
                    int tod = c - day * NT;
                    int k   = k0 + kk;
                    float v = W1[day * D + k] + W1[(NDAY + tod) * D + k] + b1[k];
                    h_sh[m][kk] = fmaxf(v, 0.0f);
                }
                __syncthreads();

                // Phase 2: thread -> cols (e, e+128), combos m0..m0+7.
                const int e    = tid & 127;
                const int half = tid >> 7;
                const int m0   = half * MPT;

                float acc0[MPT], acc1[MPT];
                const float i0 = (ks == 0) ? b2[e]       : 0.0f;
                const float i1 = (ks == 0) ? b2[e + 128] : 0.0f;
                #pragma unroll
                for (int m = 0; m < MPT; m++) { acc0[m] = i0; acc1[m] = i1; }

                #pragma unroll
                for (int kk = 0; kk < KQ; kk += 4) {
                    const float* w = W2 + (size_t)(k0 + kk) * D + e;
                    float wa0 = w[0 * D],       wa1 = w[1 * D];
                    float wa2 = w[2 * D],       wa3 = w[3 * D];
                    float wb0 = w[0 * D + 128], wb1 = w[1 * D + 128];
                    float wb2 = w[2 * D + 128], wb3 = w[3 * D + 128];
                    #pragma unroll
                    for (int m = 0; m < MPT; m++) {
                        float4 h4 = *reinterpret_cast<const float4*>(&h_sh[m0 + m][kk]);
                        acc0[m] = fmaf(h4.x, wa0, acc0[m]);
                        acc0[m] = fmaf(h4.y, wa1, acc0[m]);
                        acc0[m] = fmaf(h4.z, wa2, acc0[m]);
                        acc0[m] = fmaf(h4.w, wa3, acc0[m]);
                        acc1[m] = fmaf(h4.x, wb0, acc1[m]);
                        acc1[m] = fmaf(h4.y, wb1, acc1[m]);
                        acc1[m] = fmaf(h4.z, wb2, acc1[m]);
                        acc1[m] = fmaf(h4.w, wb3, acc1[m]);
                    }
                }

                float* __restrict__ part = g_part[ks];
                #pragma unroll
                for (int m = 0; m < MPT; m++) {
                    part[(size_t)(c0 + m0 + m) * D + e]       = acc0[m];
                    part[(size_t)(c0 + m0 + m) * D + e + 128] = acc1[m];
                }

                __threadfence();
                __syncthreads();
                if (tid == 0) atomicAdd(&g_done_mb[mb], 1u);
            }
            __syncthreads();   // protect h_sh / s_task reuse across tasks
        }
        return;
    }

    // =============================== writer ===============================
    const int wb   = bx - NBUILDERS;        // 0..295
    const int lane = tid & 31;
    const int warp = tid >> 5;

    __shared__ __align__(16) float row_sh[D];

    for (int c = wb; c < NC; c += NWRITERS) {
        const int mb = c / MTILE;

        // Acquire: scatter complete + this mb's 8 partials complete.
        if (tid == 0) {
            while (atomicAdd(&g_scat_done, 0u) < (unsigned)NTASK_SCAT) __nanosleep(128);
            while (atomicAdd(&g_done_mb[mb], 0u) < (unsigned)KSPLIT)   __nanosleep(128);
            __threadfence();
        }
        __syncthreads();

        // Reduce the 8 partials for this combo's row into shared.
        if (tid < 64) {
            const size_t base = (size_t)c * (D / 4) + tid;
            float4 s = reinterpret_cast<const float4*>(g_part[0])[base];
            #pragma unroll
            for (int p = 1; p < KSPLIT; p++) {
                float4 v = reinterpret_cast<const float4*>(g_part[p])[base];
                s.x += v.x; s.y += v.y; s.z += v.z; s.w += v.w;
            }
            reinterpret_cast<float4*>(row_sh)[tid] = s;
        }
        __syncthreads();

        float4 v0 = reinterpret_cast<const float4*>(row_sh)[lane];
        float4 v1 = reinterpret_cast<const float4*>(row_sh)[lane + 32];

        int cnt = g_cnt[c];
        if (cnt > CAP) cnt = CAP;
        const int* __restrict__ list = g_rowlist + c * CAP;

        for (int i = warp; i < cnt; i += 8) {
            int rr = __ldg(&list[i]);
            float4* __restrict__ dst = reinterpret_cast<float4*>(out + (size_t)rr * D);
            __stcs(dst + lane,      v0);
            __stcs(dst + lane + 32, v1);
        }

        // Self-reset bookkeeping for the next graph replay.
        __syncthreads();
        if (tid == 0) {
            g_cnt[c] = 0;
            unsigned p = atomicAdd(&g_wpass_mb[mb], 1u);
            if (p == (unsigned)(MTILE - 1)) {
                g_done_mb[mb]  = 0u;
                g_wpass_mb[mb] = 0u;
            }
            unsigned q = atomicAdd(&g_wpass_total, 1u);
            if (q == (unsigned)(NC - 1)) {
                g_scat_done   = 0u;
                g_task        = 0u;
                g_wpass_total = 0u;
            }
        }
        __syncthreads();   // row_sh reuse guard
    }
}

// -------------------------------------------------------------------------
// Launch. Inputs resolved by element count:
//   TE = d_in[0]; W1: 295*256 = 75520; W2: 256*256 = 65536; b1/b2: 256 each.
// -------------------------------------------------------------------------
extern "C" void kernel_launch(void* const* d_in, const int* in_sizes, int n_in,
                              void* d_out, int out_size)
{
    const void* TE = d_in[0];
    const float* W1 = nullptr;
    const float* b1 = nullptr;
    const float* W2 = nullptr;
    const float* b2 = nullptr;

    for (int j = 1; j < n_in; j++) {
        int sz = in_sizes[j];
        if (sz == (NDAY + NT) * D) {
            W1 = (const float*)d_in[j];
        } else if (sz == D * D) {
            W2 = (const float*)d_in[j];
        } else if (sz == D) {
            if (!b1) b1 = (const float*)d_in[j];
            else     b2 = (const float*)d_in[j];
        }
    }
    if (!W1 || !b1 || !W2 || !b2) return;

    fused_pipeline<<<GRID, 256>>>(W1, b1, W2, b2, TE, (float*)d_out);
}

// round 12
// speedup vs baseline: 1.5441x; 1.5441x over previous
#include <cuda_runtime.h>

#define D      256
#define NDAY   7
#define NT     288
#define NC     (NDAY * NT)        // 2016 distinct (day, tod) combos
#define ROWS   (64 * 2048)        // B * S = 131072
#define MTILE  16                 // combos per m-block
#define NMB    (NC / MTILE)       // 126 m-blocks
#define KSPLIT 8                  // k-eighths
#define KQ     (D / KSPLIT)       // 32 k-values per build block
#define MPT    (MTILE / 2)        // 8 combos per thread (2 column-halves)
#define CAP    256                // bucket capacity (mean 65, max ~105)

#define NBLK_SCAT  (ROWS / 256)   // 512 scatter blocks (FIRST in grid)
#define NBLK_BUILD (NMB * KSPLIT) // 1008 build blocks (mb-major after scatter)
#define NBLK_PRIM  (NBLK_SCAT + NBLK_BUILD)   // 1520

// K-split partial sums of the combo table. 8 x 2 MB. b2 folded into part 0.
__device__ float    g_part[KSPLIT][NC * D];
// Per-combo row buckets (self-resetting).
__device__ int      g_cnt[NC];
__device__ int      g_rowlist[NC * CAP];
// Flags (self-resetting; zero at module load).
__device__ unsigned g_scat_done;          // target NBLK_SCAT
__device__ unsigned g_done_mb[NMB];       // target KSPLIT
__device__ unsigned g_wpass_mb[NMB];      // MTILE write blocks per mb
__device__ unsigned g_wpass_total;        // NC write blocks overall

// -------------------------------------------------------------------------
// Primary kernel: blocks [0,512) scatter rows into buckets; blocks
// [512,1520) compute partial GEMMs (mb-major: early mbs finish first).
// Every block triggers PDL launch_dependents at entry so write_out's blocks
// can be placed into SM slots as primary blocks retire — HW-scheduled
// overlap, no manual partitioning (which failed in R10/R11).
// -------------------------------------------------------------------------
__global__ void __launch_bounds__(256) build_and_scatter(
    const float* __restrict__ W1, const float* __restrict__ b1,
    const float* __restrict__ W2, const float* __restrict__ b2,
    const void* __restrict__ TEp)
{
    asm volatile("griddepcontrol.launch_dependents;" ::: "memory");

    const int bx  = blockIdx.x;
    const int tid = threadIdx.x;

    if (bx < NBLK_SCAT) {
        // ---- scatter block ----
        // Per-warp TE dtype detect: values 0..287 -> int64 layout has
        // all-zero high 32-bit words; int32 layout has random indices.
        const int lane = tid & 31;
        const unsigned long long* TE64 = (const unsigned long long*)TEp;
        unsigned long long hv = (TE64[lane] >> 32) | (TE64[lane + 32] >> 32);
        bool is64 = (__ballot_sync(0xffffffffu, hv != 0ULL) == 0u);

        const int row = bx * 256 + tid;
        int t0, t1;
        if (is64) {
            longlong2 te = reinterpret_cast<const longlong2*>(TEp)[row];
            t0 = (int)te.x; t1 = (int)te.y;
        } else {
            int2 te = reinterpret_cast<const int2*>(TEp)[row];
            t0 = te.x; t1 = te.y;
        }
        int day = t0 % NDAY; day += (day >> 31) & NDAY;
        int tod = t1 % NT;   tod += (tod >> 31) & NT;
        int c   = day * NT + tod;
        int slot = atomicAdd(&g_cnt[c], 1);
        if (slot < CAP) g_rowlist[c * CAP + slot] = row;

        __threadfence();
        __syncthreads();
        if (tid == 0) atomicAdd(&g_scat_done, 1u);
        return;
    }

    // ---- build block: partial GEMM for (mb, ks) ----
    const int b  = bx - NBLK_SCAT;
    const int mb = b >> 3;
    const int ks = b & 7;
    const int c0 = mb * MTILE;
    const int k0 = ks * KQ;

    __shared__ __align__(16) float h_sh[MTILE][KQ];   // 2 KB

    // Phase 1: h slice. 16*32 = 512 values, 256 threads.
    #pragma unroll
    for (int it = 0; it < (MTILE * KQ) / 256; it++) {
        int idx = it * 256 + tid;
        int m   = idx >> 5;            // /KQ
        int kk  = idx & (KQ - 1);
        int c   = c0 + m;
        int day = c / NT;
        int tod = c - day * NT;
        int k   = k0 + kk;
        float v = W1[day * D + k] + W1[(NDAY + tod) * D + k] + b1[k];
        h_sh[m][kk] = fmaxf(v, 0.0f);
    }
    __syncthreads();

    // Phase 2: thread -> cols (e, e+128), combos m0..m0+7.
    const int e    = tid & 127;
    const int half = tid >> 7;
    const int m0   = half * MPT;

    float acc0[MPT], acc1[MPT];
    const float i0 = (ks == 0) ? b2[e]       : 0.0f;
    const float i1 = (ks == 0) ? b2[e + 128] : 0.0f;
    #pragma unroll
    for (int m = 0; m < MPT; m++) { acc0[m] = i0; acc1[m] = i1; }

    #pragma unroll
    for (int kk = 0; kk < KQ; kk += 4) {
        const float* w = W2 + (size_t)(k0 + kk) * D + e;
        float wa0 = w[0 * D],       wa1 = w[1 * D];
        float wa2 = w[2 * D],       wa3 = w[3 * D];
        float wb0 = w[0 * D + 128], wb1 = w[1 * D + 128];
        float wb2 = w[2 * D + 128], wb3 = w[3 * D + 128];
        #pragma unroll
        for (int m = 0; m < MPT; m++) {
            float4 h4 = *reinterpret_cast<const float4*>(&h_sh[m0 + m][kk]);
            acc0[m] = fmaf(h4.x, wa0, acc0[m]);
            acc0[m] = fmaf(h4.y, wa1, acc0[m]);
            acc0[m] = fmaf(h4.z, wa2, acc0[m]);
            acc0[m] = fmaf(h4.w, wa3, acc0[m]);
            acc1[m] = fmaf(h4.x, wb0, acc1[m]);
            acc1[m] = fmaf(h4.y, wb1, acc1[m]);
            acc1[m] = fmaf(h4.z, wb2, acc1[m]);
            acc1[m] = fmaf(h4.w, wb3, acc1[m]);
        }
    }

    float* __restrict__ part = g_part[ks];
    #pragma unroll
    for (int m = 0; m < MPT; m++) {
        part[(size_t)(c0 + m0 + m) * D + e]       = acc0[m];
        part[(size_t)(c0 + m0 + m) * D + e + 128] = acc1[m];
    }

    __threadfence();
    __syncthreads();
    if (tid == 0) atomicAdd(&g_done_mb[mb], 1u);
}

// -------------------------------------------------------------------------
// Secondary (PDL): block per combo. Waits on flags (atomic spin + acquire
// fence — PDL memory semantics not relied upon), reduces the 8 partials,
// streams the 1 KB row to every bucket row with __stcs, then self-resets
// all bookkeeping for the next graph replay.
// -------------------------------------------------------------------------
__global__ void __launch_bounds__(256) write_out(float* __restrict__ out)
{
    __shared__ __align__(16) float row_sh[D];

    const int c    = blockIdx.x;
    const int mb   = c / MTILE;
    const int tid  = threadIdx.x;
    const int lane = tid & 31;
    const int warp = tid >> 5;

    if (tid == 0) {
        while (atomicAdd(&g_scat_done, 0u) < (unsigned)NBLK_SCAT) __nanosleep(128);
        while (atomicAdd(&g_done_mb[mb], 0u) < (unsigned)KSPLIT)  __nanosleep(128);
        __threadfence();
    }
    __syncthreads();

    if (tid < 64) {
        const size_t base = (size_t)c * (D / 4) + tid;
        float4 s = reinterpret_cast<const float4*>(g_part[0])[base];
        #pragma unroll
        for (int p = 1; p < KSPLIT; p++) {
            float4 v = reinterpret_cast<const float4*>(g_part[p])[base];
            s.x += v.x; s.y += v.y; s.z += v.z; s.w += v.w;
        }
        reinterpret_cast<float4*>(row_sh)[tid] = s;
    }
    __syncthreads();

    float4 v0 = reinterpret_cast<const float4*>(row_sh)[lane];
    float4 v1 = reinterpret_cast<const float4*>(row_sh)[lane + 32];

    int cnt = g_cnt[c];
    if (cnt > CAP) cnt = CAP;
    const int* __restrict__ list = g_rowlist + c * CAP;

    for (int i = warp; i < cnt; i += 8) {
        int r = __ldg(&list[i]);
        float4* __restrict__ dst = reinterpret_cast<float4*>(out + (size_t)r * D);
        __stcs(dst + lane,      v0);
        __stcs(dst + lane + 32, v1);
    }

    // Self-reset for next replay (everyone already consumed the flags).
    __syncthreads();
    if (tid == 0) {
        g_cnt[c] = 0;
        unsigned p = atomicAdd(&g_wpass_mb[mb], 1u);
        if (p == (unsigned)(MTILE - 1)) {
            g_done_mb[mb]  = 0u;
            g_wpass_mb[mb] = 0u;
        }
        unsigned q = atomicAdd(&g_wpass_total, 1u);
        if (q == (unsigned)(NC - 1)) {
            g_scat_done   = 0u;
            g_wpass_total = 0u;
        }
    }
}

// -------------------------------------------------------------------------
// Launch. write_out goes out with programmatic stream serialization so its
// blocks start filling SM slots as build_and_scatter blocks retire.
// Inputs resolved by element count:
//   TE = d_in[0]; W1: 295*256 = 75520; W2: 256*256 = 65536; b1/b2: 256 each.
// -------------------------------------------------------------------------
extern "C" void kernel_launch(void* const* d_in, const int* in_sizes, int n_in,
                              void* d_out, int out_size)
{
    const void* TE = d_in[0];
    const float* W1 = nullptr;
    const float* b1 = nullptr;
    const float* W2 = nullptr;
    const float* b2 = nullptr;

    for (int j = 1; j < n_in; j++) {
        int sz = in_sizes[j];
        if (sz == (NDAY + NT) * D) {
            W1 = (const float*)d_in[j];
        } else if (sz == D * D) {
            W2 = (const float*)d_in[j];
        } else if (sz == D) {
            if (!b1) b1 = (const float*)d_in[j];
            else     b2 = (const float*)d_in[j];
        }
    }
    if (!W1 || !b1 || !W2 || !b2) return;

    float* out = (float*)d_out;

    build_and_scatter<<<NBLK_PRIM, 256>>>(W1, b1, W2, b2, TE);

    cudaLaunchConfig_t cfg = {};
    cfg.gridDim  = dim3(NC, 1, 1);
    cfg.blockDim = dim3(256, 1, 1);
    cfg.dynamicSmemBytes = 0;
    cfg.stream = 0;
    cudaLaunchAttribute attr[1];
    attr[0].id = cudaLaunchAttributeProgrammaticStreamSerialization;
    attr[0].val.programmaticStreamSerializationAllowed = 1;
    cfg.attrs = attr;
    cfg.numAttrs = 1;
    cudaLaunchKernelEx(&cfg, write_out, out);
}